// round 14
// baseline (speedup 1.0000x reference)
#include <cuda_runtime.h>
#include <cuda_bf16.h>
#include <stdint.h>
#include <math.h>

// out[i] = center[argmin_m |x[i] - center[m]|]  (exact jnp.argmin, first-min
// wins). Forward value of the straight-through soft quantizer.
//
// prep: 8192-cell Voronoi interval table, 4B/cell. Pure cells hold the winning
// center VALUE. Boundary cells hold NaN|boundary_id -> 15-entry pair table for
// the exact tie-ordered 2-way fp32 compare. Tag 0x20 -> exact 16-way scan.

#define NC      16
#define NCELLS  8192
#define U_SLACK 4e-6f   // u-units; cell width 1.22e-4; fp32 map error ~5e-7

__device__ float  g_cells[NCELLS];
__device__ float2 g_pairs[NC - 1];   // tie-ordered (p wins ties) per boundary
__device__ float2 g_affine;          // {S, B}: u = fma(x, S, B)

// ---------------------------------------------------------------- prep ----
__global__ void prep_kernel(const float* __restrict__ center) {
    __shared__ float s_val[NC];
    __shared__ int   s_orig[NC];
    __shared__ float s_thr[NC - 1];
    __shared__ float s_SB[2];

    int t = threadIdx.x;

    if (t < NC) {                         // stable rank sort
        float ct = center[t];
        int rank = 0;
        for (int j = 0; j < NC; ++j) {
            float cj = center[j];
            if (cj < ct || (cj == ct && j < t)) rank++;
        }
        s_val[rank]  = ct;
        s_orig[rank] = t;
    }
    __syncthreads();
    if (t < NC - 1) s_thr[t] = 0.5f * (s_val[t] + s_val[t + 1]);
    __syncthreads();
    if (t == 0) {
        float lo = s_thr[0], hi = s_thr[NC - 2];
        float span = hi - lo;
        float S = 0.0f, B = 1.5f;         // degenerate default -> scan tag
        if (span > 0.0f && isfinite(span) && isfinite(lo)) {
            float Sc = 1.0f / span;
            float Bc = 1.0f - lo * Sc;
            if (isfinite(Sc) && isfinite(Bc)) { S = Sc; B = Bc; }
        }
        s_SB[0] = S; s_SB[1] = B;
        if (blockIdx.x == 0) g_affine = make_float2(S, B);
    }
    __syncthreads();

    // Pair table: boundary r separates sorted r / r+1; p = tie winner = lower
    // ORIGINAL index (jnp.argmin first-wins).
    if (blockIdx.x == 0 && t < NC - 1) {
        float a = s_val[t], b = s_val[t + 1];
        float2 pq;
        if (s_orig[t] < s_orig[t + 1]) { pq.x = a; pq.y = b; }
        else                           { pq.x = b; pq.y = a; }
        g_pairs[t] = pq;
    }

    float S = s_SB[0], B = s_SB[1];
    bool degen = (S == 0.0f);

    int j0 = blockIdx.x * blockDim.x + t;
    int jstride = gridDim.x * blockDim.x;
    for (int j = j0; j < NCELLS; j += jstride) {
        float cell;
        if (degen) {
            cell = __int_as_float(0x7FC00020);          // full-scan tag
        } else {
            float ulo = 1.0f + (float)j * (1.0f / NCELLS);       // exact fp32
            float uhi = 1.0f + (float)(j + 1) * (1.0f / NCELLS); // exact fp32
            int klo = 0, nb = 0, bidx = 0;
#pragma unroll
            for (int r = 0; r < NC - 1; ++r) {
                float ur = fmaf(s_thr[r], S, B);
                if (ur <= ulo - U_SLACK)      klo++;
                else if (ur < uhi + U_SLACK) { nb++; bidx = r; }
            }
            if (nb == 0)      cell = s_val[klo];        // pure: value direct
            else if (nb == 1) cell = __int_as_float(0x7FC00000 | bidx);
            else              cell = __int_as_float(0x7FC00020);
        }
        g_cells[j] = cell;
    }
}

// ---------------------------------------------------------------- main ----
__device__ __forceinline__ float quant1(float x, float S, float B,
                                        const float* __restrict__ cells,
                                        const float2* __restrict__ pairs,
                                        const float* __restrict__ co) {
    float u = fmaf(x, S, B);
    u = fminf(fmaxf(u, 1.0f), __uint_as_float(0x3FFFFFFFu));  // clamp [1, 2)
    unsigned j = (__float_as_uint(u) >> 10) & 0x1FFFu;        // floor((u-1)*8192)
    float r = cells[j];
    if (__builtin_expect(r != r, 0)) {        // rare: boundary / degenerate
        unsigned m = __float_as_uint(r);
        if (!(m & 0x20u)) {
            float2 pq = pairs[m & 0x1Fu];     // exact 2-way, tie -> p
            r = (fabsf(x - pq.y) < fabsf(x - pq.x)) ? pq.y : pq.x;
        } else {                               // exact 16-way scan, first-min
            float bd = fabsf(x - co[0]);
            r = co[0];
#pragma unroll
            for (int k = 1; k < NC; ++k) {
                float d = fabsf(x - co[k]);
                if (d < bd) { bd = d; r = co[k]; }
            }
        }
    }
    return r;
}

__device__ __forceinline__ float4 quant4(float4 v, float S, float B,
                                         const float* __restrict__ cells,
                                         const float2* __restrict__ pairs,
                                         const float* __restrict__ co) {
    float4 r;
    r.x = quant1(v.x, S, B, cells, pairs, co);
    r.y = quant1(v.y, S, B, cells, pairs, co);
    r.z = quant1(v.z, S, B, cells, pairs, co);
    r.w = quant1(v.w, S, B, cells, pairs, co);
    return r;
}

__global__ void __launch_bounds__(256) main_kernel(
    const float4* __restrict__ x4, float4* __restrict__ out4, int n4,
    const float* __restrict__ x, float* __restrict__ out,
    int tail_start, int n, const float* __restrict__ center)
{
    __shared__ float  s_cells[NCELLS];     // 32 KB
    __shared__ float2 s_pairs[NC - 1];
    __shared__ float  s_co[NC];

    {
        const float4* __restrict__ gsrc = (const float4*)g_cells;
        float4* __restrict__ sdst = (float4*)s_cells;
#pragma unroll
        for (int i = threadIdx.x; i < NCELLS / 4; i += 256) sdst[i] = gsrc[i];
        if (threadIdx.x < NC - 1) s_pairs[threadIdx.x] = g_pairs[threadIdx.x];
        if (threadIdx.x < NC)     s_co[threadIdx.x]    = center[threadIdx.x];
    }
    __syncthreads();

    float2 SB = g_affine;
    float S = SB.x, Bc = SB.y;

    int stride = gridDim.x * blockDim.x;
    int i0 = blockIdx.x * blockDim.x + threadIdx.x;

    // 2x unrolled grid-stride: both loads in flight before either lookup.
    int i = i0;
    for (; i + stride < n4; i += 2 * stride) {
        float4 a = x4[i];
        float4 b = x4[i + stride];
        float4 ra = quant4(a, S, Bc, s_cells, s_pairs, s_co);
        float4 rb = quant4(b, S, Bc, s_cells, s_pairs, s_co);
        out4[i] = ra;
        out4[i + stride] = rb;
    }
    for (; i < n4; i += stride) {
        out4[i] = quant4(x4[i], S, Bc, s_cells, s_pairs, s_co);
    }
    for (int k = tail_start + i0; k < n; k += stride) {
        out[k] = quant1(x[k], S, Bc, s_cells, s_pairs, s_co);
    }
}

// -------------------------------------------------------------- launch ----
extern "C" void kernel_launch(void* const* d_in, const int* in_sizes, int n_in,
                              void* d_out, int out_size) {
    const float* xp     = (const float*)d_in[0];
    const float* center = (const float*)d_in[1];
    float* outp         = (float*)d_out;

    int n = in_sizes[0];

    prep_kernel<<<32, 256>>>(center);    // fp32-only

    bool aligned = ((((uintptr_t)xp) | ((uintptr_t)outp)) & 0xF) == 0;
    int n4 = aligned ? (n >> 2) : 0;
    int tail_start = n4 << 2;

    // regs=40 -> 6 blocks/SM; 148 SMs x 6 = one exact resident wave.
    int blocks = 148 * 6;
    main_kernel<<<blocks, 256>>>((const float4*)xp, (float4*)outp, n4,
                                 xp, outp, tail_start, n, center);
}

// round 16
// speedup vs baseline: 1.1939x; 1.1939x over previous
#include <cuda_runtime.h>
#include <cuda_bf16.h>
#include <stdint.h>
#include <math.h>

// out[i] = center[argmin_m |x[i] - center[m]|]  (exact jnp.argmin, first-min
// wins). Forward value of the straight-through soft quantizer.
//
// prep (fp32): 1024-cell Voronoi interval table, float2 candidates per cell.
// main: stage table to smem, stream x: FFMA + bit-trick index, one LDS.64,
// exact branchless 2-way fp32 distance compare (tie -> lower original index).

#define NC      16
#define NCELLS  1024
#define U_SLACK 4e-6f   // u-units; cell width 9.77e-4; fp32 map error ~5e-7
#define TPB     512

__device__ float2 g_cells[NCELLS];
__device__ float2 g_affine;   // {S, B}: u = fma(x, S, B)

// ---------------------------------------------------------------- prep ----
__global__ void prep_kernel(const float* __restrict__ center) {
    __shared__ float s_val[NC];
    __shared__ int   s_orig[NC];
    __shared__ float s_thr[NC - 1];
    __shared__ float s_SB[2];

    int t = threadIdx.x;

    if (t < NC) {                         // stable rank sort
        float ct = center[t];
        int rank = 0;
        for (int j = 0; j < NC; ++j) {
            float cj = center[j];
            if (cj < ct || (cj == ct && j < t)) rank++;
        }
        s_val[rank]  = ct;
        s_orig[rank] = t;
    }
    __syncthreads();
    if (t < NC - 1) s_thr[t] = 0.5f * (s_val[t] + s_val[t + 1]);
    __syncthreads();
    if (t == 0) {
        float lo = s_thr[0], hi = s_thr[NC - 2];
        float span = hi - lo;
        float S = 0.0f, B = 1.5f;         // degenerate default -> sentinel table
        if (span > 0.0f && isfinite(span) && isfinite(lo)) {
            float Sc = 1.0f / span;
            float Bc = 1.0f - lo * Sc;
            if (isfinite(Sc) && isfinite(Bc)) { S = Sc; B = Bc; }
        }
        s_SB[0] = S; s_SB[1] = B;
        if (blockIdx.x == 0) g_affine = make_float2(S, B);
    }
    __syncthreads();

    float S = s_SB[0], B = s_SB[1];
    bool degen = (S == 0.0f);

    int j0 = blockIdx.x * blockDim.x + t;
    int jstride = gridDim.x * blockDim.x;
    for (int j = j0; j < NCELLS; j += jstride) {
        float2 pq;
        if (degen) {
            pq.x = __int_as_float(0x7FC00000);   // NaN sentinel -> exact scan
            pq.y = pq.x;
        } else {
            float ulo = 1.0f + (float)j * (1.0f / NCELLS);       // exact fp32
            float uhi = 1.0f + (float)(j + 1) * (1.0f / NCELLS); // exact fp32
            int klo = 0, nb = 0;
#pragma unroll
            for (int r = 0; r < NC - 1; ++r) {
                float ur = fmaf(s_thr[r], S, B);
                if (ur <= ulo - U_SLACK)      klo++;
                else if (ur < uhi + U_SLACK)  nb++;
            }
            if (nb == 0) {
                pq.x = s_val[klo]; pq.y = s_val[klo];
            } else if (nb == 1) {
                // p (stored first) wins exact fp32 ties -> lower ORIGINAL
                // index (jnp.argmin first-wins).
                float a = s_val[klo], b = s_val[klo + 1];
                if (s_orig[klo] < s_orig[klo + 1]) { pq.x = a; pq.y = b; }
                else                               { pq.x = b; pq.y = a; }
            } else {
                pq.x = __int_as_float(0x7FC00000);
                pq.y = pq.x;
            }
        }
        g_cells[j] = pq;
    }
}

// ---------------------------------------------------------------- main ----
__device__ __forceinline__ float quant1(float x, float S, float B,
                                        const float2* __restrict__ cells,
                                        const float* __restrict__ co) {
    float u = fmaf(x, S, B);
    u = fminf(fmaxf(u, 1.0f), __uint_as_float(0x3FFFFFFFu));  // clamp [1, 2)
    unsigned j = (__float_as_uint(u) >> 13) & 0x3FFu;         // floor((u-1)*1024)
    float2 pq = cells[j];
    float dP = x - pq.x;
    float dQ = x - pq.y;
    float r = (fabsf(dQ) < fabsf(dP)) ? pq.y : pq.x;          // tie -> p
    if (r != r) {  // NaN sentinel (degenerate table): exact 16-way scan
        float bd = fabsf(x - co[0]);
        r = co[0];
#pragma unroll
        for (int m = 1; m < NC; ++m) {
            float d = fabsf(x - co[m]);
            if (d < bd) { bd = d; r = co[m]; }
        }
    }
    return r;
}

__device__ __forceinline__ float4 quant4(float4 v, float S, float B,
                                         const float2* __restrict__ cells,
                                         const float* __restrict__ co) {
    float4 r;
    r.x = quant1(v.x, S, B, cells, co);
    r.y = quant1(v.y, S, B, cells, co);
    r.z = quant1(v.z, S, B, cells, co);
    r.w = quant1(v.w, S, B, cells, co);
    return r;
}

__global__ void __launch_bounds__(TPB) main_kernel(
    const float4* __restrict__ x4, float4* __restrict__ out4, int n4,
    const float* __restrict__ x, float* __restrict__ out,
    int tail_start, int n, const float* __restrict__ center)
{
    __shared__ float2 s_cells[NCELLS];   // 8 KB
    __shared__ float  s_co[NC];

    int stride = gridDim.x * blockDim.x;
    int i0 = blockIdx.x * blockDim.x + threadIdx.x;

    // Peel: issue the first pair of global loads BEFORE staging + sync, so
    // their latency overlaps the table copy.
    int i = i0;
    float4 a0, b0;
    bool have = (i + stride < n4);
    if (have) { a0 = x4[i]; b0 = x4[i + stride]; }

    {
        const float4* __restrict__ gsrc = (const float4*)g_cells;
        float4* __restrict__ sdst = (float4*)s_cells;
#pragma unroll
        for (int k = threadIdx.x; k < NCELLS / 2; k += TPB) sdst[k] = gsrc[k];
        if (threadIdx.x < NC) s_co[threadIdx.x] = center[threadIdx.x];
    }
    __syncthreads();

    float2 SB = g_affine;
    float S = SB.x, Bc = SB.y;

    if (have) {
        out4[i]          = quant4(a0, S, Bc, s_cells, s_co);
        out4[i + stride] = quant4(b0, S, Bc, s_cells, s_co);
        i += 2 * stride;
    }

    // 2x unrolled grid-stride (champion hot loop, unchanged).
    for (; i + stride < n4; i += 2 * stride) {
        float4 a = x4[i];
        float4 b = x4[i + stride];
        float4 ra = quant4(a, S, Bc, s_cells, s_co);
        float4 rb = quant4(b, S, Bc, s_cells, s_co);
        out4[i] = ra;
        out4[i + stride] = rb;
    }
    for (; i < n4; i += stride) {
        out4[i] = quant4(x4[i], S, Bc, s_cells, s_co);
    }
    for (int k = tail_start + i0; k < n; k += stride) {
        out[k] = quant1(x[k], S, Bc, s_cells, s_co);
    }
}

// -------------------------------------------------------------- launch ----
extern "C" void kernel_launch(void* const* d_in, const int* in_sizes, int n_in,
                              void* d_out, int out_size) {
    const float* xp     = (const float*)d_in[0];
    const float* center = (const float*)d_in[1];
    float* outp         = (float*)d_out;

    int n = in_sizes[0];

    prep_kernel<<<8, 128>>>(center);     // fp32-only, 1024 cells

    bool aligned = ((((uintptr_t)xp) | ((uintptr_t)outp)) & 0xF) == 0;
    int n4 = aligned ? (n >> 2) : 0;
    int tail_start = n4 << 2;

    // 1536 threads/SM (reg-limited), 148 SMs x 3 blocks = one exact wave.
    int blocks = 148 * 3;
    main_kernel<<<blocks, TPB>>>((const float4*)xp, (float4*)outp, n4,
                                 xp, outp, tail_start, n, center);
}

// round 17
// speedup vs baseline: 1.2018x; 1.0066x over previous
#include <cuda_runtime.h>
#include <cuda_bf16.h>
#include <stdint.h>
#include <math.h>

// out[i] = center[argmin_m |x[i] - center[m]|]  (exact jnp.argmin, first-min
// wins). Forward value of the straight-through soft quantizer.
//
// Single fused kernel (512 thr, 444 blocks): each block builds a 1024-cell
// Voronoi interval table in smem (2 cells/thread, fp32 u-space), then streams
// x with the frozen champion hot loop: FFMA + bit-trick index, one LDS.64,
// exact branchless 2-way fp32 compare (tie -> lower original index).

#define NC      16
#define NCELLS  1024
#define U_SLACK 4e-6f   // u-units; cell width 9.77e-4; fp32 map error ~5e-7
#define TPB     512

__device__ __forceinline__ float quant1(float x, float S, float B,
                                        const float2* __restrict__ cells,
                                        const float* __restrict__ co) {
    float u = fmaf(x, S, B);
    u = fminf(fmaxf(u, 1.0f), __uint_as_float(0x3FFFFFFFu));  // clamp [1, 2)
    unsigned j = (__float_as_uint(u) >> 13) & 0x3FFu;         // floor((u-1)*1024)
    float2 pq = cells[j];
    float dP = x - pq.x;
    float dQ = x - pq.y;
    float r = (fabsf(dQ) < fabsf(dP)) ? pq.y : pq.x;          // tie -> p
    if (r != r) {  // NaN sentinel (degenerate table): exact 16-way scan
        float bd = fabsf(x - co[0]);
        r = co[0];
#pragma unroll
        for (int m = 1; m < NC; ++m) {
            float d = fabsf(x - co[m]);
            if (d < bd) { bd = d; r = co[m]; }
        }
    }
    return r;
}

__device__ __forceinline__ float4 quant4(float4 v, float S, float B,
                                         const float2* __restrict__ cells,
                                         const float* __restrict__ co) {
    float4 r;
    r.x = quant1(v.x, S, B, cells, co);
    r.y = quant1(v.y, S, B, cells, co);
    r.z = quant1(v.z, S, B, cells, co);
    r.w = quant1(v.w, S, B, cells, co);
    return r;
}

__global__ void __launch_bounds__(TPB) fused_kernel(
    const float4* __restrict__ x4, float4* __restrict__ out4, int n4,
    const float* __restrict__ x, float* __restrict__ out,
    int tail_start, int n, const float* __restrict__ center)
{
    __shared__ float2 s_cells[NCELLS];   // 8 KB
    __shared__ float  s_co[NC];
    __shared__ float  s_val[NC];
    __shared__ int    s_orig[NC];
    __shared__ float  s_thr[NC - 1];
    __shared__ float  s_SB[2];

    int t = threadIdx.x;
    int stride = gridDim.x * blockDim.x;
    int i0 = blockIdx.x * blockDim.x + t;

    // Peel: first pair of global loads issued BEFORE the table build, so their
    // latency overlaps it.
    int i = i0;
    float4 a0, b0;
    bool have = (i + stride < n4);
    if (have) { a0 = x4[i]; b0 = x4[i + stride]; }

    // --- build phase (2 cells/thread; deterministic, identical per block) ---
    if (t < NC) {
        float ct = center[t];
        s_co[t] = ct;
        int rank = 0;                    // stable rank sort
        for (int j = 0; j < NC; ++j) {
            float cj = center[j];
            if (cj < ct || (cj == ct && j < t)) rank++;
        }
        s_val[rank]  = ct;
        s_orig[rank] = t;
    }
    __syncthreads();
    if (t < NC - 1) s_thr[t] = 0.5f * (s_val[t] + s_val[t + 1]);
    __syncthreads();
    if (t == 0) {
        float lo = s_thr[0], hi = s_thr[NC - 2];
        float span = hi - lo;
        float S = 0.0f, B = 1.5f;        // degenerate default -> sentinel table
        if (span > 0.0f && isfinite(span) && isfinite(lo)) {
            float Sc = 1.0f / span;
            float Bc = 1.0f - lo * Sc;
            if (isfinite(Sc) && isfinite(Bc)) { S = Sc; B = Bc; }
        }
        s_SB[0] = S; s_SB[1] = B;
    }
    __syncthreads();

    float S = s_SB[0], Bc = s_SB[1];
    {
        bool degen = (S == 0.0f);
#pragma unroll
        for (int c = 0; c < NCELLS / TPB; ++c) {
            int j = t + c * TPB;
            float2 pq;
            if (degen) {
                pq.x = __int_as_float(0x7FC00000);  // NaN -> exact scan
                pq.y = pq.x;
            } else {
                float ulo = 1.0f + (float)j * (1.0f / NCELLS);       // exact
                float uhi = 1.0f + (float)(j + 1) * (1.0f / NCELLS); // exact
                int klo = 0, nb = 0;
#pragma unroll
                for (int r = 0; r < NC - 1; ++r) {
                    float ur = fmaf(s_thr[r], S, Bc);
                    if (ur <= ulo - U_SLACK)      klo++;
                    else if (ur < uhi + U_SLACK)  nb++;
                }
                if (nb == 0) {
                    pq.x = s_val[klo]; pq.y = s_val[klo];
                } else if (nb == 1) {
                    // p (stored first) wins exact fp32 ties -> lower ORIGINAL
                    // index (jnp.argmin first-wins).
                    float a = s_val[klo], b = s_val[klo + 1];
                    if (s_orig[klo] < s_orig[klo + 1]) { pq.x = a; pq.y = b; }
                    else                               { pq.x = b; pq.y = a; }
                } else {
                    pq.x = __int_as_float(0x7FC00000);
                    pq.y = pq.x;
                }
            }
            s_cells[j] = pq;
        }
    }
    __syncthreads();

    // --- stream phase (frozen champion hot loop) ---
    if (have) {
        out4[i]          = quant4(a0, S, Bc, s_cells, s_co);
        out4[i + stride] = quant4(b0, S, Bc, s_cells, s_co);
        i += 2 * stride;
    }
    for (; i + stride < n4; i += 2 * stride) {
        float4 a = x4[i];
        float4 b = x4[i + stride];
        float4 ra = quant4(a, S, Bc, s_cells, s_co);
        float4 rb = quant4(b, S, Bc, s_cells, s_co);
        out4[i] = ra;
        out4[i + stride] = rb;
    }
    for (; i < n4; i += stride) {
        out4[i] = quant4(x4[i], S, Bc, s_cells, s_co);
    }
    for (int k = tail_start + i0; k < n; k += stride) {
        out[k] = quant1(x[k], S, Bc, s_cells, s_co);
    }
}

// -------------------------------------------------------------- launch ----
extern "C" void kernel_launch(void* const* d_in, const int* in_sizes, int n_in,
                              void* d_out, int out_size) {
    const float* xp     = (const float*)d_in[0];
    const float* center = (const float*)d_in[1];
    float* outp         = (float*)d_out;

    int n = in_sizes[0];

    bool aligned = ((((uintptr_t)xp) | ((uintptr_t)outp)) & 0xF) == 0;
    int n4 = aligned ? (n >> 2) : 0;
    int tail_start = n4 << 2;

    // 1536 threads/SM (reg-limited), 148 SMs x 3 blocks = one exact wave.
    int blocks = 148 * 3;
    fused_kernel<<<blocks, TPB>>>((const float4*)xp, (float4*)outp, n4,
                                  xp, outp, tail_start, n, center);
}